// round 10
// baseline (speedup 1.0000x reference)
#include <cuda_runtime.h>
#include <cuda_bf16.h>
#include <cstdint>

// ---------------------------------------------------------------------------
// RNNEncDec: persistent recurrence (R5, proven) + pipelined bf16 HMMA logits
// GEMM (3-stage cp.async, ldmatrix fragment loads, 2 CTAs/SM) with fused
// partial logsumexp. tcgen05 unavailable (harness ptxas targets sm_103).
// ---------------------------------------------------------------------------

#define H     300
#define BATCH 256
#define NX    128
#define NY    128
#define V     32000
#define MROWS (127 * 256)      // 32512
#define KPA   320              // padded K: 5 chunks of 64; bias baked at col 304
#define NTILE 250              // 32000 / 128
#define MTILE 254              // 32512 / 128

// gemm pipeline geometry
#define SKS        72                      // smem chunk row stride (halves)
#define STG_BYTES  (256 * SKS * 2)         // 36864 per stage (A 128 rows + W 128)
#define NSTG       3
#define SMEM_G     (NSTG * STG_BYTES)      // 110592

// recurrence persistent kernel geometry (unchanged)
#define GRID_R 100
#define JT     12
#define BT     64
#define CH     100
#define SM_W    0
#define SM_B    (2 * JT * H * 4)
#define SM_BUF0 29696
#define SM_BUF1 (SM_BUF0 + CH * BT * 4)
#define SMEM_R  (SM_BUF1 + CH * BT * 4)    // 80896

// ------------------------- device scratch -----------------------------------
__device__ float g_h[2][H * BATCH];
__device__ __align__(16) __nv_bfloat16 g_A[(size_t)MROWS * KPA];
__device__ __align__(16) __nv_bfloat16 g_Wb[(size_t)V * KPA];
__device__ float g_pM[(size_t)MROWS * NTILE];
__device__ float g_pS[(size_t)MROWS * NTILE];
__device__ float g_bsum[4064];
__device__ unsigned g_barCnt;
__device__ unsigned g_barGen;

// ------------------------- helpers ------------------------------------------
__device__ __forceinline__ void cpa16(void* dst, const void* src) {
    uint32_t d = (uint32_t)__cvta_generic_to_shared(dst);
    asm volatile("cp.async.cg.shared.global [%0], [%1], 16;\n" :: "r"(d), "l"(src));
}
#define CPA_COMMIT() asm volatile("cp.async.commit_group;\n" ::: "memory")
#define CPA_WAIT1()  asm volatile("cp.async.wait_group 1;\n" ::: "memory")
#define CPA_WAIT0()  asm volatile("cp.async.wait_group 0;\n" ::: "memory")

__device__ __forceinline__ void mma16816(float* c, const uint32_t* a,
                                         uint32_t b0, uint32_t b1) {
    asm volatile(
        "mma.sync.aligned.m16n8k16.row.col.f32.bf16.bf16.f32 "
        "{%0,%1,%2,%3}, {%4,%5,%6,%7}, {%8,%9}, {%0,%1,%2,%3};\n"
        : "+f"(c[0]), "+f"(c[1]), "+f"(c[2]), "+f"(c[3])
        : "r"(a[0]), "r"(a[1]), "r"(a[2]), "r"(a[3]), "r"(b0), "r"(b1));
}

__device__ __forceinline__ void ldsm4(uint32_t* r, uint32_t addr) {
    asm volatile(
        "ldmatrix.sync.aligned.m8n8.x4.shared.b16 {%0,%1,%2,%3}, [%4];"
        : "=r"(r[0]), "=r"(r[1]), "=r"(r[2]), "=r"(r[3]) : "r"(addr));
}

// ------------------------- init (each replay) -------------------------------
__global__ void k_init() {
    int i = blockIdx.x * blockDim.x + threadIdx.x;
    if (i == 0) { g_barCnt = 0; g_barGen = 0; }
    if (i < H * BATCH) g_h[0][i] = 0.f;
    if (i < MROWS * 20) {                       // A pad cols 300..319
        int row = i / 20, c = i - row * 20;
        g_A[(size_t)row * KPA + 300 + c] = __float2bfloat16(c == 4 ? 1.f : 0.f);
    }
}

// ------------------------- outW -> bf16 padded, bias baked at col 304 -------
__global__ void k_convW(const float* __restrict__ outW,
                        const float* __restrict__ outb) {
    int i = blockIdx.x * blockDim.x + threadIdx.x;   // < V*80
    if (i >= V * 80) return;
    int n = i / 80, kq = i - n * 80;
    int k = kq * 4;
    float4 v = make_float4(0.f, 0.f, 0.f, 0.f);
    if (k < 300) v = *reinterpret_cast<const float4*>(outW + (size_t)n * H + k);
    if (k == 304) v.x = outb[n];
    __nv_bfloat162 p0 = __floats2bfloat162_rn(v.x, v.y);
    __nv_bfloat162 p1 = __floats2bfloat162_rn(v.z, v.w);
    uint2 pk = make_uint2(*(uint32_t*)&p0, *(uint32_t*)&p1);
    *reinterpret_cast<uint2*>(g_Wb + (size_t)n * KPA + k) = pk;
}

// ------------------------- grid barrier (recurrence) ------------------------
__device__ __forceinline__ void gridbar(unsigned gen) {
    __threadfence();
    __syncthreads();
    if (threadIdx.x == 0) {
        unsigned t = atomicAdd(&g_barCnt, 1u);
        if (t == GRID_R - 1) {
            g_barCnt = 0;
            __threadfence();
            atomicExch(&g_barGen, gen);
        } else {
            unsigned v;
            do {
                asm volatile("ld.global.cg.u32 %0, [%1];" : "=r"(v) : "l"(&g_barGen));
                if (v >= gen) break;
                __nanosleep(40);
            } while (true);
        }
        __threadfence();
    }
    __syncthreads();
}

// ------------------------- persistent recurrence (R5, proven) ---------------
__global__ void __launch_bounds__(256, 1) k_recur(
    const int*   __restrict__ x,
    const int*   __restrict__ y,
    const float* __restrict__ enc_emb,
    const float* __restrict__ encW,
    const float* __restrict__ encb,
    const float* __restrict__ dec_emb,
    const float* __restrict__ decW,
    const float* __restrict__ decb)
{
    extern __shared__ __align__(16) unsigned char smem[];
    float* sW   = reinterpret_cast<float*>(smem + SM_W);
    float* sb   = reinterpret_cast<float*>(smem + SM_B);
    float* buf0 = reinterpret_cast<float*>(smem + SM_BUF0);
    float* buf1 = reinterpret_cast<float*>(smem + SM_BUF1);

    int tid = threadIdx.x;
    int bx  = blockIdx.x;
    int j0  = (bx >> 2) * JT;
    int b0  = (bx & 3) * BT;
    int bl  = tid & 63;
    int jg  = tid >> 6;
    int jA  = j0 + jg * 3;

    for (int i = tid; i < 2 * JT * H; i += 256) {
        int bank = i / (JT * H);
        int r    = i - bank * (JT * H);
        int j    = r / H, k = r - j * H;
        const float* src = bank ? decW : encW;
        sW[i] = src[(size_t)(j0 + j) * H + k];
    }
    if (tid < JT)          sb[tid] = encb[j0 + tid];
    else if (tid < 2 * JT) sb[tid] = decb[j0 + tid - JT];
    __syncthreads();

    for (int s = 0; s < 255; ++s) {
        const float* hin  = g_h[s & 1];
        float*       hout = g_h[(s & 1) ^ 1];
        int dec = (s >= NX);
        int t   = s - NX;
        const int*   idxp = dec ? (y + t * BATCH) : (x + s * BATCH);
        const float* embp = dec ? dec_emb : enc_emb;
        const float* Wb   = sW + dec * (JT * H);
        const float* bb   = sb + dec * JT;

        int e = idxp[b0 + bl];
        const float* erow = embp + (size_t)e * H + jA;
        float e0 = __ldg(erow), e1 = __ldg(erow + 1), e2 = __ldg(erow + 2);

        #pragma unroll 4
        for (int i = tid; i < CH * 16; i += 256) {
            int k = i >> 4, bq = i & 15;
            cpa16(buf0 + k * BT + bq * 4, hin + k * BATCH + b0 + bq * 4);
        }
        CPA_COMMIT();
        #pragma unroll 4
        for (int i = tid; i < CH * 16; i += 256) {
            int k = i >> 4, bq = i & 15;
            cpa16(buf1 + k * BT + bq * 4, hin + (CH + k) * BATCH + b0 + bq * 4);
        }
        CPA_COMMIT();

        float a0 = 0.f, a1 = 0.f, a2 = 0.f;

        CPA_WAIT1();
        __syncthreads();
        #pragma unroll 5
        for (int kk = 0; kk < CH; kk += 4) {
            float h0 = buf0[(kk + 0) * BT + bl];
            float h1 = buf0[(kk + 1) * BT + bl];
            float h2 = buf0[(kk + 2) * BT + bl];
            float h3 = buf0[(kk + 3) * BT + bl];
            float4 w;
            w = *reinterpret_cast<const float4*>(Wb + (jg * 3 + 0) * H + kk);
            a0 = fmaf(h3, w.w, fmaf(h2, w.z, fmaf(h1, w.y, fmaf(h0, w.x, a0))));
            w = *reinterpret_cast<const float4*>(Wb + (jg * 3 + 1) * H + kk);
            a1 = fmaf(h3, w.w, fmaf(h2, w.z, fmaf(h1, w.y, fmaf(h0, w.x, a1))));
            w = *reinterpret_cast<const float4*>(Wb + (jg * 3 + 2) * H + kk);
            a2 = fmaf(h3, w.w, fmaf(h2, w.z, fmaf(h1, w.y, fmaf(h0, w.x, a2))));
        }
        __syncthreads();

        #pragma unroll 4
        for (int i = tid; i < CH * 16; i += 256) {
            int k = i >> 4, bq = i & 15;
            cpa16(buf0 + k * BT + bq * 4, hin + (2 * CH + k) * BATCH + b0 + bq * 4);
        }
        CPA_COMMIT();

        CPA_WAIT1();
        __syncthreads();
        #pragma unroll 5
        for (int kk = 0; kk < CH; kk += 4) {
            float h0 = buf1[(kk + 0) * BT + bl];
            float h1 = buf1[(kk + 1) * BT + bl];
            float h2 = buf1[(kk + 2) * BT + bl];
            float h3 = buf1[(kk + 3) * BT + bl];
            float4 w;
            w = *reinterpret_cast<const float4*>(Wb + (jg * 3 + 0) * H + CH + kk);
            a0 = fmaf(h3, w.w, fmaf(h2, w.z, fmaf(h1, w.y, fmaf(h0, w.x, a0))));
            w = *reinterpret_cast<const float4*>(Wb + (jg * 3 + 1) * H + CH + kk);
            a1 = fmaf(h3, w.w, fmaf(h2, w.z, fmaf(h1, w.y, fmaf(h0, w.x, a1))));
            w = *reinterpret_cast<const float4*>(Wb + (jg * 3 + 2) * H + CH + kk);
            a2 = fmaf(h3, w.w, fmaf(h2, w.z, fmaf(h1, w.y, fmaf(h0, w.x, a2))));
        }

        CPA_WAIT0();
        __syncthreads();
        #pragma unroll 5
        for (int kk = 0; kk < CH; kk += 4) {
            float h0 = buf0[(kk + 0) * BT + bl];
            float h1 = buf0[(kk + 1) * BT + bl];
            float h2 = buf0[(kk + 2) * BT + bl];
            float h3 = buf0[(kk + 3) * BT + bl];
            float4 w;
            w = *reinterpret_cast<const float4*>(Wb + (jg * 3 + 0) * H + 2 * CH + kk);
            a0 = fmaf(h3, w.w, fmaf(h2, w.z, fmaf(h1, w.y, fmaf(h0, w.x, a0))));
            w = *reinterpret_cast<const float4*>(Wb + (jg * 3 + 1) * H + 2 * CH + kk);
            a1 = fmaf(h3, w.w, fmaf(h2, w.z, fmaf(h1, w.y, fmaf(h0, w.x, a1))));
            w = *reinterpret_cast<const float4*>(Wb + (jg * 3 + 2) * H + 2 * CH + kk);
            a2 = fmaf(h3, w.w, fmaf(h2, w.z, fmaf(h1, w.y, fmaf(h0, w.x, a2))));
        }

        float v0 = fmaxf(a0 + e0 + bb[jg * 3 + 0], 0.f);
        float v1 = fmaxf(a1 + e1 + bb[jg * 3 + 1], 0.f);
        float v2 = fmaxf(a2 + e2 + bb[jg * 3 + 2], 0.f);
        int b = b0 + bl;
        hout[(jA + 0) * BATCH + b] = v0;
        hout[(jA + 1) * BATCH + b] = v1;
        hout[(jA + 2) * BATCH + b] = v2;
        if (dec) {
            __nv_bfloat16* ap = g_A + ((size_t)t * BATCH + b) * KPA + jA;
            ap[0] = __float2bfloat16(v0);
            ap[1] = __float2bfloat16(v1);
            ap[2] = __float2bfloat16(v2);
        }

        gridbar((unsigned)(s + 1));
    }
}

// ------------------------- pipelined GEMM + fused partial logsumexp ---------
// grid (NTILE, MTILE), 256 threads (8 warps: 4 M x 2 N), tile 128x128,
// K=320 in 5 chunks of 64, 3-stage cp.async pipeline, ldmatrix frag loads.
__global__ void __launch_bounds__(256, 2) k_gemm() {
    extern __shared__ __align__(16) unsigned char smem_raw[];

    int tid = threadIdx.x;
    int m0 = blockIdx.y * 128;
    int n0 = blockIdx.x * 128;

    // stage chunk kc into stage buffer stg: 256 rows (128 A + 128 W) x 128B
    auto stage = [&](int kc, int stg) {
        char* bb = (char*)smem_raw + stg * STG_BYTES;
        #pragma unroll
        for (int p = 0; p < 8; p++) {
            int i = tid + p * 256;            // 0..2047
            int r = i >> 3, j = i & 7;
            const char* src = (r < 128)
                ? (const char*)(g_A  + (size_t)(m0 + r)       * KPA + kc * 64)
                : (const char*)(g_Wb + (size_t)(n0 + r - 128) * KPA + kc * 64);
            cpa16(bb + r * (SKS * 2) + j * 16, src + j * 16);
        }
        CPA_COMMIT();
    };

    stage(0, 0);
    stage(1, 1);

    int warp = tid >> 5, lane = tid & 31;
    int wm = warp & 3, wn = warp >> 2;
    int g = lane >> 2, tig = lane & 3;
    int lr = lane & 15, lh = lane >> 4;      // ldmatrix row-in-16 / k-half

    float acc[2][8][4];
    #pragma unroll
    for (int a = 0; a < 2; a++)
        #pragma unroll
        for (int b = 0; b < 8; b++)
            #pragma unroll
            for (int q = 0; q < 4; q++) acc[a][b][q] = 0.f;

    #pragma unroll 1
    for (int kc = 0; kc < 5; kc++) {
        if (kc < 4) { CPA_WAIT1(); } else { CPA_WAIT0(); }
        __syncthreads();                     // stage kc ready; all done reading
        if (kc + 2 < 5) stage(kc + 2, (kc + 2) % NSTG);

        const __nv_bfloat16* As = reinterpret_cast<const __nv_bfloat16*>(
            (char*)smem_raw + (kc % NSTG) * STG_BYTES);
        const __nv_bfloat16* Ws = As + 128 * SKS;

        // per-thread ldmatrix base addresses for this stage
        uint32_t aAdr0 = (uint32_t)__cvta_generic_to_shared(
            As + (wm * 32 + lr) * SKS + lh * 8);
        uint32_t aAdr1 = aAdr0 + 16 * SKS * 2;
        uint32_t bAdr[4];
        #pragma unroll
        for (int p = 0; p < 4; p++)
            bAdr[p] = (uint32_t)__cvta_generic_to_shared(
                Ws + (wn * 64 + p * 16 + lr) * SKS + lh * 8);

        #pragma unroll
        for (int ki = 0; ki < 4; ki++) {
            uint32_t kb = (uint32_t)(ki * 32);   // bytes: 16 halves
            uint32_t av0[4], av1[4];
            ldsm4(av0, aAdr0 + kb);
            ldsm4(av1, aAdr1 + kb);
            #pragma unroll
            for (int p = 0; p < 4; p++) {
                uint32_t bv[4];
                ldsm4(bv, bAdr[p] + kb);
                // bv: r0=b0(nt=2p), r1=b0(nt=2p+1), r2=b1(nt=2p), r3=b1(nt=2p+1)
                mma16816(acc[0][2 * p],     av0, bv[0], bv[2]);
                mma16816(acc[0][2 * p + 1], av0, bv[1], bv[3]);
                mma16816(acc[1][2 * p],     av1, bv[0], bv[2]);
                mma16816(acc[1][2 * p + 1], av1, bv[1], bv[3]);
            }
        }
    }
    __syncthreads();   // done with tiles; smem reused for row reduction

    // per-row max / sumexp over this CTA's 128 columns (bias already baked)
    float rm[4], rs[4];
    #pragma unroll
    for (int r = 0; r < 4; r++) {
        int mt = r >> 1, hi = r & 1;
        float mx = -3.4e38f;
        #pragma unroll
        for (int nt = 0; nt < 8; nt++) {
            mx = fmaxf(mx, acc[mt][nt][hi * 2]);
            mx = fmaxf(mx, acc[mt][nt][hi * 2 + 1]);
        }
        mx = fmaxf(mx, __shfl_xor_sync(0xffffffffu, mx, 1));
        mx = fmaxf(mx, __shfl_xor_sync(0xffffffffu, mx, 2));
        float s = 0.f;
        #pragma unroll
        for (int nt = 0; nt < 8; nt++) {
            s += __expf(acc[mt][nt][hi * 2]     - mx);
            s += __expf(acc[mt][nt][hi * 2 + 1] - mx);
        }
        s += __shfl_xor_sync(0xffffffffu, s, 1);
        s += __shfl_xor_sync(0xffffffffu, s, 2);
        rm[r] = mx; rs[r] = s;
    }

    float* red = reinterpret_cast<float*>(smem_raw);   // 128 rows * 2 floats
    if (wn == 0 && tig == 0) {
        #pragma unroll
        for (int r = 0; r < 4; r++) {
            int rowL = wm * 32 + (r >> 1) * 16 + (r & 1) * 8 + g;
            red[rowL * 2]     = rm[r];
            red[rowL * 2 + 1] = rs[r];
        }
    }
    __syncthreads();
    if (wn == 1 && tig == 0) {
        #pragma unroll
        for (int r = 0; r < 4; r++) {
            int rowL = wm * 32 + (r >> 1) * 16 + (r & 1) * 8 + g;
            float om = red[rowL * 2], os = red[rowL * 2 + 1];
            float nm = fmaxf(rm[r], om);
            float s  = rs[r] * __expf(rm[r] - nm) + os * __expf(om - nm);
            size_t grow = (size_t)(m0 + rowL);
            g_pM[grow * NTILE + blockIdx.x] = nm;
            g_pS[grow * NTILE + blockIdx.x] = s;
        }
    }
}

// ------------------------- per-row lse + target logit -> CE -----------------
__global__ void __launch_bounds__(256) k_reduce(const int* __restrict__ y) {
    int warp = threadIdx.x >> 5, lane = threadIdx.x & 31;
    int row = blockIdx.x * 8 + warp;
    int t = row >> 8, b = row & 255;
    int n = y[(t + 1) * BATCH + b];

    const __nv_bfloat16* Ar = g_A  + (size_t)row * KPA;
    const __nv_bfloat16* Wr = g_Wb + (size_t)n   * KPA;
    float dot = 0.f;
    for (int k = lane; k < KPA; k += 32)
        dot += __bfloat162float(Ar[k]) * __bfloat162float(Wr[k]);
    #pragma unroll
    for (int o = 16; o; o >>= 1) dot += __shfl_xor_sync(0xffffffffu, dot, o);

    float m = -3.4e38f, s = 0.f;
    for (int i = lane; i < NTILE; i += 32) {
        float tm = g_pM[(size_t)row * NTILE + i];
        float ts = g_pS[(size_t)row * NTILE + i];
        float nm = fmaxf(m, tm);
        s = s * __expf(m - nm) + ts * __expf(tm - nm);
        m = nm;
    }
    #pragma unroll
    for (int o = 16; o; o >>= 1) {
        float om = __shfl_xor_sync(0xffffffffu, m, o);
        float os = __shfl_xor_sync(0xffffffffu, s, o);
        float nm = fmaxf(m, om);
        s = s * __expf(m - nm) + os * __expf(om - nm);
        m = nm;
    }
    float ce = (m + __logf(s)) - dot;

    __shared__ float sm[8];
    if (lane == 0) sm[warp] = ce;
    __syncthreads();
    if (threadIdx.x == 0) {
        float tt = 0.f;
        #pragma unroll
        for (int i = 0; i < 8; i++) tt += sm[i];
        g_bsum[blockIdx.x] = tt;
    }
}

// ------------------------- final deterministic sum --------------------------
__global__ void k_final(float* out) {
    __shared__ double sm[256];
    int tid = threadIdx.x;
    double s = 0.0;
    for (int i = tid; i < 4064; i += 256) s += (double)g_bsum[i];
    sm[tid] = s;
    __syncthreads();
    for (int o = 128; o; o >>= 1) {
        if (tid < o) sm[tid] += sm[tid + o];
        __syncthreads();
    }
    if (tid == 0) out[0] = (float)(sm[0] * (1.0 / 256.0));
}

// ------------------------- launch -------------------------------------------
extern "C" void kernel_launch(void* const* d_in, const int* in_sizes, int n_in,
                              void* d_out, int out_size) {
    const int*   x       = (const int*)  d_in[0];
    const int*   y       = (const int*)  d_in[1];
    const float* enc_emb = (const float*)d_in[2];
    const float* encW    = (const float*)d_in[3];
    const float* encb    = (const float*)d_in[4];
    const float* dec_emb = (const float*)d_in[5];
    const float* decW    = (const float*)d_in[6];
    const float* decb    = (const float*)d_in[7];
    const float* outW    = (const float*)d_in[8];
    const float* outb    = (const float*)d_in[9];
    float* out = (float*)d_out;

    cudaFuncSetAttribute(k_recur, cudaFuncAttributeMaxDynamicSharedMemorySize,
                         SMEM_R);
    cudaFuncSetAttribute(k_gemm, cudaFuncAttributeMaxDynamicSharedMemorySize,
                         SMEM_G);

    k_init<<<(MROWS * 20 + 255) / 256, 256>>>();
    k_convW<<<(V * 80 + 255) / 256, 256>>>(outW, outb);

    k_recur<<<GRID_R, 256, SMEM_R>>>(x, y, enc_emb, encW, encb,
                                     dec_emb, decW, decb);

    k_gemm<<<dim3(NTILE, MTILE), 256, SMEM_G>>>();
    k_reduce<<<4064, 256>>>(y);
    k_final<<<1, 256>>>(out);
}

// round 11
// speedup vs baseline: 1.7507x; 1.7507x over previous
#include <cuda_runtime.h>
#include <cuda_bf16.h>
#include <cstdint>

// ---------------------------------------------------------------------------
// RNNEncDec: persistent recurrence + pipelined bf16 HMMA logits GEMM where
// BOTH operands are pre-stored in mma-fragment order (all smem operand loads
// are LDS.128), 3-stage cp.async, 2 CTAs/SM, fused partial logsumexp.
// ---------------------------------------------------------------------------

#define H     300
#define BATCH 256
#define NX    128
#define NY    128
#define V     32000
#define MROWS (127 * 256)      // 32512 = 254 * 128
#define KPA   320              // padded K: 5 chunks of 64; bias baked at col 304
#define NTILE 250              // 32000 / 128
#define MTILE 254              // 32512 / 128

// gemm pipeline geometry (fragment layout: no padding needed)
#define STG_BYTES  32768                   // 16KB A-frags + 16KB B-frags
#define NSTG       3
#define SMEM_G     (NSTG * STG_BYTES)      // 98304

// recurrence persistent kernel geometry (unchanged)
#define GRID_R 100
#define JT     12
#define BT     64
#define CH     100
#define SM_W    0
#define SM_B    (2 * JT * H * 4)
#define SM_BUF0 29696
#define SM_BUF1 (SM_BUF0 + CH * BT * 4)
#define SMEM_R  (SM_BUF1 + CH * BT * 4)    // 80896

// ------------------------- device scratch -----------------------------------
__device__ float g_h[2][H * BATCH];
__device__ __align__(16) __nv_bfloat16 g_AF[(size_t)MROWS * KPA];  // frag layout
__device__ __align__(16) __nv_bfloat16 g_WF[(size_t)V * KPA];      // frag layout
__device__ float g_pM[(size_t)MROWS * NTILE];
__device__ float g_pS[(size_t)MROWS * NTILE];
__device__ float g_bsum[4064];
__device__ unsigned g_barCnt;
__device__ unsigned g_barGen;

// ------------------------- fragment-layout index maps ------------------------
// A element (m, k) -> element index in g_AF.
// Layout: [mb 254][wm 4][mt 2][kc 5][ki 4][lane 32][16B = reg*4 + kbit*2]
__device__ __forceinline__ size_t af_idx(int m, int k) {
    int mb = m >> 7, rl = m & 127;
    int wm = rl >> 5, r32 = rl & 31;
    int mt = r32 >> 4, rr = r32 & 15;
    int half = rr >> 3, g = rr & 7;          // a0/a2 rows vs a1/a3 rows
    int kc = k >> 6, kk = k & 63;
    int ki = kk >> 4, kt = kk & 15;
    int khalf = kt >> 3, kp = kt & 7;        // a0/a1 (k) vs a2/a3 (k+8)
    int tig = kp >> 1, kbit = kp & 1;
    int lane = g * 4 + tig;
    int reg = half + khalf * 2;
    size_t byte = (size_t)mb * 81920 +
        (size_t)(((((wm * 2 + mt) * 5 + kc) * 4 + ki) * 512) +
                 lane * 16 + reg * 4 + kbit * 2);
    return byte >> 1;
}

// W element (n, k) -> element index in g_WF.
// Layout: [nb 250][wn 2][nt 8][kc 5][kpair 2][lane 32][16B = kilo*8+regB*4+kbit*2]
__device__ __forceinline__ size_t wf_idx(int n, int k) {
    int nb = n >> 7, nl = n & 127;
    int wn = nl >> 6, nt = (nl >> 3) & 7, g = nl & 7;
    int kc = k >> 6, kk = k & 63;
    int ki = kk >> 4, kt = kk & 15;
    int khalf = kt >> 3, kp = kt & 7;        // b0 (k) vs b1 (k+8)
    int tig = kp >> 1, kbit = kp & 1;
    int kpair = ki >> 1, kilo = ki & 1;
    int lane = g * 4 + tig;
    size_t byte = (size_t)nb * 81920 +
        (size_t)((((((wn * 8 + nt) * 5 + kc) * 2 + kpair) * 512)) +
                 lane * 16 + kilo * 8 + khalf * 4 + kbit * 2);
    return byte >> 1;
}

// ------------------------- helpers ------------------------------------------
__device__ __forceinline__ void cpa16(void* dst, const void* src) {
    uint32_t d = (uint32_t)__cvta_generic_to_shared(dst);
    asm volatile("cp.async.cg.shared.global [%0], [%1], 16;\n" :: "r"(d), "l"(src));
}
#define CPA_COMMIT() asm volatile("cp.async.commit_group;\n" ::: "memory")
#define CPA_WAIT1()  asm volatile("cp.async.wait_group 1;\n" ::: "memory")
#define CPA_WAIT0()  asm volatile("cp.async.wait_group 0;\n" ::: "memory")

__device__ __forceinline__ void mma16816(float* c, const uint32_t* a,
                                         uint32_t b0, uint32_t b1) {
    asm volatile(
        "mma.sync.aligned.m16n8k16.row.col.f32.bf16.bf16.f32 "
        "{%0,%1,%2,%3}, {%4,%5,%6,%7}, {%8,%9}, {%0,%1,%2,%3};\n"
        : "+f"(c[0]), "+f"(c[1]), "+f"(c[2]), "+f"(c[3])
        : "r"(a[0]), "r"(a[1]), "r"(a[2]), "r"(a[3]), "r"(b0), "r"(b1));
}

__device__ __forceinline__ void lds128(uint32_t* r, uint32_t addr) {
    asm volatile("ld.shared.v4.u32 {%0,%1,%2,%3}, [%4];"
        : "=r"(r[0]), "=r"(r[1]), "=r"(r[2]), "=r"(r[3]) : "r"(addr));
}

// ------------------------- init (each replay) -------------------------------
__global__ void k_init() {
    int i = blockIdx.x * blockDim.x + threadIdx.x;
    if (i == 0) { g_barCnt = 0; g_barGen = 0; }
    if (i < H * BATCH) g_h[0][i] = 0.f;
    if (i < MROWS * 20) {                       // A pad cols 300..319
        int m = i / 20, c = i - m * 20;
        int k = 300 + c;
        g_AF[af_idx(m, k)] = __float2bfloat16(k == 304 ? 1.f : 0.f);
    }
}

// ------------------------- outW -> fragment-layout bf16, bias at col 304 ----
// One thread builds one 16B chunk (8 bf16, single n, 8 scattered k).
__global__ void k_convW(const float* __restrict__ outW,
                        const float* __restrict__ outb) {
    int c = blockIdx.x * blockDim.x + threadIdx.x;   // < 250*5120
    if (c >= NTILE * 5120) return;
    int nb = c / 5120, ci = c - nb * 5120;
    int lane = ci & 31;
    int t1 = ci >> 5;
    int kpair = t1 & 1;
    int t2 = t1 >> 1;
    int kc = t2 % 5;
    int c2 = t2 / 5;                 // wn*8+nt
    int g = lane >> 2, tig = lane & 3;
    int n = nb * 128 + c2 * 8 + g;   // c2 already encodes wn*8+nt over 16 values

    __nv_bfloat16 vals[8];
    #pragma unroll
    for (int e = 0; e < 8; e++) {
        int kilo = e >> 2, khalf = (e >> 1) & 1, kbit = e & 1;
        int k = kc * 64 + (kpair * 2 + kilo) * 16 + khalf * 8 + tig * 2 + kbit;
        float v = 0.f;
        if (k < 300)      v = outW[(size_t)n * H + k];
        else if (k == 304) v = outb[n];
        vals[e] = __float2bfloat16(v);
    }
    *reinterpret_cast<uint4*>(g_WF + (size_t)c * 8) =
        *reinterpret_cast<uint4*>(vals);
}

// ------------------------- grid barrier (recurrence) ------------------------
__device__ __forceinline__ void gridbar(unsigned gen) {
    __threadfence();
    __syncthreads();
    if (threadIdx.x == 0) {
        unsigned t = atomicAdd(&g_barCnt, 1u);
        if (t == GRID_R - 1) {
            g_barCnt = 0;
            __threadfence();
            atomicExch(&g_barGen, gen);
        } else {
            unsigned v;
            do {
                asm volatile("ld.global.cg.u32 %0, [%1];" : "=r"(v) : "l"(&g_barGen));
                if (v >= gen) break;
                __nanosleep(40);
            } while (true);
        }
        __threadfence();
    }
    __syncthreads();
}

// ------------------------- persistent recurrence ----------------------------
__global__ void __launch_bounds__(256, 1) k_recur(
    const int*   __restrict__ x,
    const int*   __restrict__ y,
    const float* __restrict__ enc_emb,
    const float* __restrict__ encW,
    const float* __restrict__ encb,
    const float* __restrict__ dec_emb,
    const float* __restrict__ decW,
    const float* __restrict__ decb)
{
    extern __shared__ __align__(16) unsigned char smem[];
    float* sW   = reinterpret_cast<float*>(smem + SM_W);
    float* sb   = reinterpret_cast<float*>(smem + SM_B);
    float* buf0 = reinterpret_cast<float*>(smem + SM_BUF0);
    float* buf1 = reinterpret_cast<float*>(smem + SM_BUF1);

    int tid = threadIdx.x;
    int bx  = blockIdx.x;
    int j0  = (bx >> 2) * JT;
    int b0  = (bx & 3) * BT;
    int bl  = tid & 63;
    int jg  = tid >> 6;
    int jA  = j0 + jg * 3;

    for (int i = tid; i < 2 * JT * H; i += 256) {
        int bank = i / (JT * H);
        int r    = i - bank * (JT * H);
        int j    = r / H, k = r - j * H;
        const float* src = bank ? decW : encW;
        sW[i] = src[(size_t)(j0 + j) * H + k];
    }
    if (tid < JT)          sb[tid] = encb[j0 + tid];
    else if (tid < 2 * JT) sb[tid] = decb[j0 + tid - JT];
    __syncthreads();

    for (int s = 0; s < 255; ++s) {
        const float* hin  = g_h[s & 1];
        float*       hout = g_h[(s & 1) ^ 1];
        int dec = (s >= NX);
        int t   = s - NX;
        const int*   idxp = dec ? (y + t * BATCH) : (x + s * BATCH);
        const float* embp = dec ? dec_emb : enc_emb;
        const float* Wb   = sW + dec * (JT * H);
        const float* bb   = sb + dec * JT;

        int e = idxp[b0 + bl];
        const float* erow = embp + (size_t)e * H + jA;
        float e0 = __ldg(erow), e1 = __ldg(erow + 1), e2 = __ldg(erow + 2);

        #pragma unroll 4
        for (int i = tid; i < CH * 16; i += 256) {
            int k = i >> 4, bq = i & 15;
            cpa16(buf0 + k * BT + bq * 4, hin + k * BATCH + b0 + bq * 4);
        }
        CPA_COMMIT();
        #pragma unroll 4
        for (int i = tid; i < CH * 16; i += 256) {
            int k = i >> 4, bq = i & 15;
            cpa16(buf1 + k * BT + bq * 4, hin + (CH + k) * BATCH + b0 + bq * 4);
        }
        CPA_COMMIT();

        float a0 = 0.f, a1 = 0.f, a2 = 0.f;

        CPA_WAIT1();
        __syncthreads();
        #pragma unroll 5
        for (int kk = 0; kk < CH; kk += 4) {
            float h0 = buf0[(kk + 0) * BT + bl];
            float h1 = buf0[(kk + 1) * BT + bl];
            float h2 = buf0[(kk + 2) * BT + bl];
            float h3 = buf0[(kk + 3) * BT + bl];
            float4 w;
            w = *reinterpret_cast<const float4*>(Wb + (jg * 3 + 0) * H + kk);
            a0 = fmaf(h3, w.w, fmaf(h2, w.z, fmaf(h1, w.y, fmaf(h0, w.x, a0))));
            w = *reinterpret_cast<const float4*>(Wb + (jg * 3 + 1) * H + kk);
            a1 = fmaf(h3, w.w, fmaf(h2, w.z, fmaf(h1, w.y, fmaf(h0, w.x, a1))));
            w = *reinterpret_cast<const float4*>(Wb + (jg * 3 + 2) * H + kk);
            a2 = fmaf(h3, w.w, fmaf(h2, w.z, fmaf(h1, w.y, fmaf(h0, w.x, a2))));
        }
        __syncthreads();

        #pragma unroll 4
        for (int i = tid; i < CH * 16; i += 256) {
            int k = i >> 4, bq = i & 15;
            cpa16(buf0 + k * BT + bq * 4, hin + (2 * CH + k) * BATCH + b0 + bq * 4);
        }
        CPA_COMMIT();

        CPA_WAIT1();
        __syncthreads();
        #pragma unroll 5
        for (int kk = 0; kk < CH; kk += 4) {
            float h0 = buf1[(kk + 0) * BT + bl];
            float h1 = buf1[(kk + 1) * BT + bl];
            float h2 = buf1[(kk + 2) * BT + bl];
            float h3 = buf1[(kk + 3) * BT + bl];
            float4 w;
            w = *reinterpret_cast<const float4*>(Wb + (jg * 3 + 0) * H + CH + kk);
            a0 = fmaf(h3, w.w, fmaf(h2, w.z, fmaf(h1, w.y, fmaf(h0, w.x, a0))));
            w = *reinterpret_cast<const float4*>(Wb + (jg * 3 + 1) * H + CH + kk);
            a1 = fmaf(h3, w.w, fmaf(h2, w.z, fmaf(h1, w.y, fmaf(h0, w.x, a1))));
            w = *reinterpret_cast<const float4*>(Wb + (jg * 3 + 2) * H + CH + kk);
            a2 = fmaf(h3, w.w, fmaf(h2, w.z, fmaf(h1, w.y, fmaf(h0, w.x, a2))));
        }

        CPA_WAIT0();
        __syncthreads();
        #pragma unroll 5
        for (int kk = 0; kk < CH; kk += 4) {
            float h0 = buf0[(kk + 0) * BT + bl];
            float h1 = buf0[(kk + 1) * BT + bl];
            float h2 = buf0[(kk + 2) * BT + bl];
            float h3 = buf0[(kk + 3) * BT + bl];
            float4 w;
            w = *reinterpret_cast<const float4*>(Wb + (jg * 3 + 0) * H + 2 * CH + kk);
            a0 = fmaf(h3, w.w, fmaf(h2, w.z, fmaf(h1, w.y, fmaf(h0, w.x, a0))));
            w = *reinterpret_cast<const float4*>(Wb + (jg * 3 + 1) * H + 2 * CH + kk);
            a1 = fmaf(h3, w.w, fmaf(h2, w.z, fmaf(h1, w.y, fmaf(h0, w.x, a1))));
            w = *reinterpret_cast<const float4*>(Wb + (jg * 3 + 2) * H + 2 * CH + kk);
            a2 = fmaf(h3, w.w, fmaf(h2, w.z, fmaf(h1, w.y, fmaf(h0, w.x, a2))));
        }

        float v0 = fmaxf(a0 + e0 + bb[jg * 3 + 0], 0.f);
        float v1 = fmaxf(a1 + e1 + bb[jg * 3 + 1], 0.f);
        float v2 = fmaxf(a2 + e2 + bb[jg * 3 + 2], 0.f);
        int b = b0 + bl;
        hout[(jA + 0) * BATCH + b] = v0;
        hout[(jA + 1) * BATCH + b] = v1;
        hout[(jA + 2) * BATCH + b] = v2;
        if (dec) {
            int m = t * BATCH + b;
            g_AF[af_idx(m, jA + 0)] = __float2bfloat16(v0);
            g_AF[af_idx(m, jA + 1)] = __float2bfloat16(v1);
            g_AF[af_idx(m, jA + 2)] = __float2bfloat16(v2);
        }

        gridbar((unsigned)(s + 1));
    }
}

// ------------------------- pipelined GEMM + fused partial logsumexp ---------
// grid (NTILE, MTILE), 256 threads (8 warps: 4 M x 2 N), tile 128x128,
// K=320 in 5 chunks of 64, 3-stage cp.async, fragment-layout LDS.128 loads.
__global__ void __launch_bounds__(256, 2) k_gemm() {
    extern __shared__ __align__(16) unsigned char smem_raw[];

    int tid = threadIdx.x;
    int mb = blockIdx.y;
    int nb = blockIdx.x;

    // stage chunk kc: A frags 8 x 2KB chunks, B frags 16 x 1KB chunks
    auto stage = [&](int kc, int stg) {
        char* bbuf = (char*)smem_raw + stg * STG_BYTES;
        const char* agl = (const char*)g_AF + (size_t)mb * 81920;
        const char* wgl = (const char*)g_WF + (size_t)nb * 81920;
        #pragma unroll
        for (int p = 0; p < 8; p++) {
            int i = tid + p * 256;              // 0..2047
            if (i < 1024) {
                int c = i >> 7, off = (i & 127) * 16;
                cpa16(bbuf + c * 2048 + off,
                      agl + (size_t)(c * 5 + kc) * 2048 + off);
            } else {
                int j = i - 1024;
                int c = j >> 6, off = (j & 63) * 16;
                cpa16(bbuf + 16384 + c * 1024 + off,
                      wgl + (size_t)(c * 5 + kc) * 1024 + off);
            }
        }
        CPA_COMMIT();
    };

    stage(0, 0);
    stage(1, 1);

    int warp = tid >> 5, lane = tid & 31;
    int wm = warp & 3, wn = warp >> 2;
    int g = lane >> 2, tig = lane & 3;

    uint32_t smem0 = (uint32_t)__cvta_generic_to_shared(smem_raw);

    float acc[2][8][4];
    #pragma unroll
    for (int a = 0; a < 2; a++)
        #pragma unroll
        for (int b = 0; b < 8; b++)
            #pragma unroll
            for (int q = 0; q < 4; q++) acc[a][b][q] = 0.f;

    #pragma unroll 1
    for (int kc = 0; kc < 5; kc++) {
        if (kc < 4) { CPA_WAIT1(); } else { CPA_WAIT0(); }
        __syncthreads();                     // stage kc ready; all done reading
        if (kc + 2 < 5) stage(kc + 2, (kc + 2) % NSTG);

        uint32_t sA = smem0 + (kc % NSTG) * STG_BYTES + lane * 16;
        uint32_t sB = sA + 16384;

        uint32_t af[2][4][4];
        #pragma unroll
        for (int mt = 0; mt < 2; mt++)
            #pragma unroll
            for (int ki = 0; ki < 4; ki++)
                lds128(af[mt][ki], sA + (uint32_t)(((wm * 2 + mt) * 4 + ki) * 512));

        #pragma unroll
        for (int nt = 0; nt < 8; nt++) {
            uint32_t bq[8];
            lds128(bq,     sB + (uint32_t)(((wn * 8 + nt) * 2 + 0) * 512));
            lds128(bq + 4, sB + (uint32_t)(((wn * 8 + nt) * 2 + 1) * 512));
            #pragma unroll
            for (int ki = 0; ki < 4; ki++) {
                uint32_t b0 = bq[(ki >> 1) * 4 + (ki & 1) * 2];
                uint32_t b1 = bq[(ki >> 1) * 4 + (ki & 1) * 2 + 1];
                mma16816(acc[0][nt], af[0][ki], b0, b1);
                mma16816(acc[1][nt], af[1][ki], b0, b1);
            }
        }
    }
    __syncthreads();   // done with tiles; smem reused for row reduction

    // per-row max / sumexp over this CTA's 128 columns (bias already baked)
    float rm[4], rs[4];
    #pragma unroll
    for (int r = 0; r < 4; r++) {
        int mt = r >> 1, hi = r & 1;
        float mx = -3.4e38f;
        #pragma unroll
        for (int nt = 0; nt < 8; nt++) {
            mx = fmaxf(mx, acc[mt][nt][hi * 2]);
            mx = fmaxf(mx, acc[mt][nt][hi * 2 + 1]);
        }
        mx = fmaxf(mx, __shfl_xor_sync(0xffffffffu, mx, 1));
        mx = fmaxf(mx, __shfl_xor_sync(0xffffffffu, mx, 2));
        float s = 0.f;
        #pragma unroll
        for (int nt = 0; nt < 8; nt++) {
            s += __expf(acc[mt][nt][hi * 2]     - mx);
            s += __expf(acc[mt][nt][hi * 2 + 1] - mx);
        }
        s += __shfl_xor_sync(0xffffffffu, s, 1);
        s += __shfl_xor_sync(0xffffffffu, s, 2);
        rm[r] = mx; rs[r] = s;
    }

    float* red = reinterpret_cast<float*>(smem_raw);   // 128 rows * 2 floats
    if (wn == 0 && tig == 0) {
        #pragma unroll
        for (int r = 0; r < 4; r++) {
            int rowL = wm * 32 + (r >> 1) * 16 + (r & 1) * 8 + g;
            red[rowL * 2]     = rm[r];
            red[rowL * 2 + 1] = rs[r];
        }
    }
    __syncthreads();
    if (wn == 1 && tig == 0) {
        #pragma unroll
        for (int r = 0; r < 4; r++) {
            int rowL = wm * 32 + (r >> 1) * 16 + (r & 1) * 8 + g;
            float om = red[rowL * 2], os = red[rowL * 2 + 1];
            float nm = fmaxf(rm[r], om);
            float s  = rs[r] * __expf(rm[r] - nm) + os * __expf(om - nm);
            size_t grow = (size_t)(mb * 128 + rowL);
            g_pM[grow * NTILE + nb] = nm;
            g_pS[grow * NTILE + nb] = s;
        }
    }
}

// ------------------------- per-row lse + target logit -> CE -----------------
__global__ void __launch_bounds__(256) k_reduce(const int* __restrict__ y) {
    int warp = threadIdx.x >> 5, lane = threadIdx.x & 31;
    int row = blockIdx.x * 8 + warp;
    int t = row >> 8, b = row & 255;
    int n = y[(t + 1) * BATCH + b];

    // dot(A[row], W[n]) over K=320 (bias baked at col 304)
    float dot = 0.f;
    for (int k = lane; k < KPA; k += 32)
        dot += __bfloat162float(g_AF[af_idx(row, k)]) *
               __bfloat162float(g_WF[wf_idx(n, k)]);
    #pragma unroll
    for (int o = 16; o; o >>= 1) dot += __shfl_xor_sync(0xffffffffu, dot, o);

    float m = -3.4e38f, s = 0.f;
    for (int i = lane; i < NTILE; i += 32) {
        float tm = g_pM[(size_t)row * NTILE + i];
        float ts = g_pS[(size_t)row * NTILE + i];
        float nm = fmaxf(m, tm);
        s = s * __expf(m - nm) + ts * __expf(tm - nm);
        m = nm;
    }
    #pragma unroll
    for (int o = 16; o; o >>= 1) {
        float om = __shfl_xor_sync(0xffffffffu, m, o);
        float os = __shfl_xor_sync(0xffffffffu, s, o);
        float nm = fmaxf(m, om);
        s = s * __expf(m - nm) + os * __expf(om - nm);
        m = nm;
    }
    float ce = (m + __logf(s)) - dot;

    __shared__ float sm[8];
    if (lane == 0) sm[warp] = ce;
    __syncthreads();
    if (threadIdx.x == 0) {
        float tt = 0.f;
        #pragma unroll
        for (int i = 0; i < 8; i++) tt += sm[i];
        g_bsum[blockIdx.x] = tt;
    }
}

// ------------------------- final deterministic sum --------------------------
__global__ void k_final(float* out) {
    __shared__ double sm[256];
    int tid = threadIdx.x;
    double s = 0.0;
    for (int i = tid; i < 4064; i += 256) s += (double)g_bsum[i];
    sm[tid] = s;
    __syncthreads();
    for (int o = 128; o; o >>= 1) {
        if (tid < o) sm[tid] += sm[tid + o];
        __syncthreads();
    }
    if (tid == 0) out[0] = (float)(sm[0] * (1.0 / 256.0));
}

// ------------------------- launch -------------------------------------------
extern "C" void kernel_launch(void* const* d_in, const int* in_sizes, int n_in,
                              void* d_out, int out_size) {
    const int*   x       = (const int*)  d_in[0];
    const int*   y       = (const int*)  d_in[1];
    const float* enc_emb = (const float*)d_in[2];
    const float* encW    = (const float*)d_in[3];
    const float* encb    = (const float*)d_in[4];
    const float* dec_emb = (const float*)d_in[5];
    const float* decW    = (const float*)d_in[6];
    const float* decb    = (const float*)d_in[7];
    const float* outW    = (const float*)d_in[8];
    const float* outb    = (const float*)d_in[9];
    float* out = (float*)d_out;

    cudaFuncSetAttribute(k_recur, cudaFuncAttributeMaxDynamicSharedMemorySize,
                         SMEM_R);
    cudaFuncSetAttribute(k_gemm, cudaFuncAttributeMaxDynamicSharedMemorySize,
                         SMEM_G);

    k_init<<<(MROWS * 20 + 255) / 256, 256>>>();
    k_convW<<<(NTILE * 5120 + 255) / 256, 256>>>(outW, outb);

    k_recur<<<GRID_R, 256, SMEM_R>>>(x, y, enc_emb, encW, encb,
                                     dec_emb, decW, decb);

    k_gemm<<<dim3(NTILE, MTILE), 256, SMEM_G>>>();
    k_reduce<<<4064, 256>>>(y);
    k_final<<<1, 256>>>(out);
}